// round 9
// baseline (speedup 1.0000x reference)
#include <cuda_runtime.h>
#include <cuda_bf16.h>
#include <cstdint>

// ---------------------------------------------------------------------------
// Convolution_29738353557732 : e3nn-style graph conv
// R9: warp-specialized k_edge (8 GEMM warps + 2 scatter warps, mbarrier ring),
//     2-nodes-per-warp node kernels.
// ---------------------------------------------------------------------------

#define NMAX 50176
typedef unsigned long long ull;

__device__ float g_f  [NMAX * 160];
__device__ float g_sc [NMAX * 160];
__device__ float g_mid[NMAX * 384];

__device__ __forceinline__ void red4(float* p, float a, float b, float c, float d) {
    asm volatile("red.global.add.v4.f32 [%0], {%1,%2,%3,%4};"
                 :: "l"(p), "f"(a), "f"(b), "f"(c), "f"(d) : "memory");
}
__device__ __forceinline__ ull fdup(float x) {
    ull r; asm("mov.b64 %0, {%1, %1};" : "=l"(r) : "f"(x)); return r;
}
__device__ __forceinline__ void ffma2(ull& acc, ull a, ull b) {
    asm("fma.rn.f32x2 %0, %1, %2, %0;" : "+l"(acc) : "l"(a), "l"(b));
}
__device__ __forceinline__ float2 funpack(ull p) {
    float lo, hi; asm("mov.b64 {%0, %1}, %2;" : "=f"(lo), "=f"(hi) : "l"(p));
    return make_float2(lo, hi);
}
__device__ __forceinline__ uint32_t smem_u32(const void* p) {
    uint32_t a;
    asm("{ .reg .u64 t; cvta.to.shared.u64 t, %1; cvt.u32.u64 %0, t; }" : "=r"(a) : "l"(p));
    return a;
}
#define MBAR_INIT(a, c) \
    asm volatile("mbarrier.init.shared.b64 [%0], %1;" :: "r"(a), "r"(c) : "memory")
#define MBAR_ARRIVE(a) \
    asm volatile("mbarrier.arrive.shared.b64 _, [%0];" :: "r"(a) : "memory")
#define MBAR_WAIT(mbar, parity) do {                                          \
    uint32_t _m = (mbar), _p = (parity), _done;                               \
    asm volatile("{\n\t.reg .pred p;\n\t"                                     \
        "mbarrier.try_wait.parity.acquire.cta.shared::cta.b64 p, [%1], %2;\n\t" \
        "selp.b32 %0, 1, 0, p;\n\t}" : "=r"(_done) : "r"(_m), "r"(_p) : "memory"); \
    if (!_done) {                                                             \
        asm volatile("{\n\t.reg .pred P1;\n\t"                                \
            "WL_%=:\n\t"                                                      \
            "mbarrier.try_wait.parity.acquire.cta.shared::cta.b64 P1, [%0], %1, 0x989680;\n\t" \
            "@P1 bra.uni WD_%=;\n\t"                                          \
            "bra.uni WL_%=;\n\t"                                              \
            "WD_%=:\n\t}" :: "r"(_m), "r"(_p) : "memory");                    \
    }                                                                         \
} while (0)
#define BARX(id, cnt) asm volatile("bar.sync %0, %1;" :: "r"(id), "r"(cnt) : "memory")

// ---------------------------------------------------------------- node pre
// 2 nodes per warp: weight LDS shared between both nodes. Also zeroes g_mid.
#define PRE_SCW0 0
#define PRE_L1W0 16384
#define PRE_SCW1 32768
#define PRE_L1W1 36864
#define PRE_X    40960
#define PRE_SMEM 51200

__global__ __launch_bounds__(256) void k_nodepre(
    const float* __restrict__ x, const float* __restrict__ attr,
    const float* __restrict__ sc_w0, const float* __restrict__ sc_w1,
    const float* __restrict__ l1w0, const float* __restrict__ l1w1, int N)
{
    extern __shared__ unsigned char sbp[];
    float* s_scw0 = (float*)(sbp + PRE_SCW0);
    float* s_l1w0 = (float*)(sbp + PRE_L1W0);
    float* s_scw1 = (float*)(sbp + PRE_SCW1);
    float* s_l1w1 = (float*)(sbp + PRE_L1W1);
    float* s_x    = (float*)(sbp + PRE_X);     // 16 rows x 160

    {   // zero g_mid (grid-stride)
        float4* m4 = reinterpret_cast<float4*>(g_mid);
        int tot = N * 96;
        int stride = gridDim.x * 256;
        for (int i = blockIdx.x * 256 + threadIdx.x; i < tot; i += stride)
            m4[i] = make_float4(0.f, 0.f, 0.f, 0.f);
    }

    for (int i = threadIdx.x; i < 4096; i += 256) { s_scw0[i] = sc_w0[i]; s_l1w0[i] = l1w0[i]; }
    for (int i = threadIdx.x; i < 1024; i += 256) { s_scw1[i] = sc_w1[i]; s_l1w1[i] = l1w1[i]; }

    int wrp = threadIdx.x >> 5, l = threadIdx.x & 31;
    int n0 = blockIdx.x * 16 + wrp * 2;
    int n1 = n0 + 1;
    bool v0 = n0 < N, v1 = n1 < N;
    float* xr0 = &s_x[(wrp * 2) * 160];
    float* xr1 = &s_x[(wrp * 2 + 1) * 160];
    if (v0) {
#pragma unroll
        for (int i = 0; i < 5; i++) xr0[l + 32 * i] = x[(size_t)n0 * 160 + l + 32 * i];
    }
    if (v1) {
#pragma unroll
        for (int i = 0; i < 5; i++) xr1[l + 32 * i] = x[(size_t)n1 * 160 + l + 32 * i];
    }
    __syncthreads();
    if (!v0) return;

    float a0 = attr[n0];
    float a1 = v1 ? attr[n1] : 0.f;
    int w_[3], d_[3];
#pragma unroll
    for (int i = 0; i < 3; i++) { int o = l + 32 * i; w_[i] = o / 3; d_[i] = o - 3 * w_[i]; }

    ull af0 = 0ull, as0 = 0ull, af1 = 0ull, as1 = 0ull;
#pragma unroll 8
    for (int u = 0; u < 64; u++) {
        ull wl = *(const ull*)&s_l1w0[u * 64 + 2 * l];
        ull ws = *(const ull*)&s_scw0[u * 64 + 2 * l];
        ull x0 = fdup(xr0[u]);
        ull x1 = fdup(xr1[u]);
        ffma2(af0, x0, wl); ffma2(as0, x0, ws);
        ffma2(af1, x1, wl); ffma2(as1, x1, ws);
    }
    float fv0[3] = {0,0,0}, sv0[3] = {0,0,0}, fv1[3] = {0,0,0}, sv1[3] = {0,0,0};
#pragma unroll 4
    for (int u = 0; u < 32; u++) {
#pragma unroll
        for (int i = 0; i < 3; i++) {
            float wl = s_l1w1[u * 32 + w_[i]];
            float ws = s_scw1[u * 32 + w_[i]];
            float xv0 = xr0[64 + 3 * u + d_[i]];
            float xv1 = xr1[64 + 3 * u + d_[i]];
            fv0[i] += xv0 * wl;  sv0[i] += xv0 * ws;
            fv1[i] += xv1 * wl;  sv1[i] += xv1 * ws;
        }
    }
    {
        float* fo = &g_f[(size_t)n0 * 160];
        float* so = &g_sc[(size_t)n0 * 160];
        float S1 = 0.125f * a0, S2 = 0.17677669529663687f * a0;
        float2 ff = funpack(af0), ss = funpack(as0);
        *(float2*)&fo[2 * l] = make_float2(ff.x * S1, ff.y * S1);
        *(float2*)&so[2 * l] = make_float2(ss.x * S1, ss.y * S1);
#pragma unroll
        for (int i = 0; i < 3; i++) {
            fo[64 + l + 32 * i] = fv0[i] * S2;
            so[64 + l + 32 * i] = sv0[i] * S2;
        }
    }
    if (v1) {
        float* fo = &g_f[(size_t)n1 * 160];
        float* so = &g_sc[(size_t)n1 * 160];
        float S1 = 0.125f * a1, S2 = 0.17677669529663687f * a1;
        float2 ff = funpack(af1), ss = funpack(as1);
        *(float2*)&fo[2 * l] = make_float2(ff.x * S1, ff.y * S1);
        *(float2*)&so[2 * l] = make_float2(ss.x * S1, ss.y * S1);
#pragma unroll
        for (int i = 0; i < 3; i++) {
            fo[64 + l + 32 * i] = fv1[i] * S2;
            so[64 + l + 32 * i] = sv1[i] * S2;
        }
    }
}

// ---------------------------------------------------------------- edge kernel
// 320 threads, 1 CTA/SM persistent. Warps 0-7 = GEMM (phase1+phase2),
// warps 8-9 = scatter (phase3). 2-stage smem ring (wt/ea/src/dst), mbarriers.
#define TILE_E 64
#define O_W2   0                       // 49152
#define O_WT   49152                   // 2 x 49152
#define O_H    147456                  // 16384
#define O_W1T  163840                  // 2048
#define O_EA   165888                  // 2 x 64 x float4 = 2048
#define O_SRC  167936                  // 2 x 256
#define O_DST  168448                  // 2 x 256
#define O_G    168960                  // 2 x 160 x 4 = 1280
#define O_MB   170240                  // 4 mbarriers
#define K9_SMEM 170496

__global__ __launch_bounds__(320, 1) void k_edge(
    const float* __restrict__ edge_attr, const float* __restrict__ edge_scalars,
    const float* __restrict__ fc_w1, const float* __restrict__ fc_w2,
    const int* __restrict__ edge_src, const int* __restrict__ edge_dst, int E)
{
    extern __shared__ unsigned char sb[];
    float*  s_w2  = (float*)(sb + O_W2);
    float*  s_h   = (float*)(sb + O_H);
    float*  s_w1t = (float*)(sb + O_W1T);
    float4* s_ea4 = (float4*)(sb + O_EA);
    int*    s_src = (int*)(sb + O_SRC);
    int*    s_dst = (int*)(sb + O_DST);
    float*  s_g   = (float*)(sb + O_G);
    const uint32_t u_mb = smem_u32(sb + O_MB);  // full0, full1, empty0, empty1

    const int tid = threadIdx.x;
    const int wrp = tid >> 5, l = tid & 31;

    if (tid == 0) {
        MBAR_INIT(u_mb + 0, 1);   // full[0]
        MBAR_INIT(u_mb + 8, 1);   // full[1]
        MBAR_INIT(u_mb + 16, 1);  // empty[0]
        MBAR_INIT(u_mb + 24, 1);  // empty[1]
    }
    for (int i = tid; i < 12288; i += 320) s_w2[i] = fc_w2[i] * 0.125f;
    for (int i = tid; i < 512; i += 320) {
        int c = i >> 6, j = i & 63;            // w1t[j*8+c] = fc_w1[c*64+j]
        s_w1t[j * 8 + c] = fc_w1[i];
    }
    __syncthreads();

    const int ntiles = (E + TILE_E - 1) / TILE_E;

    if (wrp < 8) {
        // ================= GEMM warps (phase1 + phase2) =================
        const int e = tid & 63, jg = tid >> 6;    // phase-1 mapping
        const int eb = wrp * 8;                   // phase-2: 8 edges/warp
        int kk = 0;
        for (int tile = blockIdx.x; tile < ntiles; tile += gridDim.x, kk++) {
            const int s = kk & 1;
            const int pe = ((kk >> 1) & 1) ^ 1;
            const int e0 = tile * TILE_E;
            const int ge = e0 + e;
            const bool gv = ge < E;

            // ---- phase 1: LDG es (+ea/src/dst for t<64), compute h -> s_h
            float4 esA = make_float4(0,0,0,0), esB = esA;
            if (gv) {
                const float4* esp = (const float4*)&edge_scalars[(size_t)ge * 8];
                esA = esp[0]; esB = esp[1];
            }
            float4 eaR = make_float4(0,0,0,0);
            int srcR = 0, dstR = 0;
            if (tid < 64) {
                int g2 = e0 + tid;
                if (g2 < E) {
                    eaR = *(const float4*)&edge_attr[(size_t)g2 * 4];
                    srcR = edge_src[g2];
                    dstR = edge_dst[g2];
                }
            }
#pragma unroll 4
            for (int jj = 0; jj < 16; jj++) {
                int j = jg * 16 + jj;
                float4 wa = *(const float4*)&s_w1t[j * 8];
                float4 wb = *(const float4*)&s_w1t[j * 8 + 4];
                float acc = esA.x * wa.x + esA.y * wa.y + esA.z * wa.z + esA.w * wa.w
                          + esB.x * wb.x + esB.y * wb.y + esB.z * wb.z + esB.w * wb.w;
                acc *= 0.3535533905932738f;
                float ex = __expf(-acc);
                s_h[j * 64 + e] = __fdividef(acc, 1.f + ex);
            }
            BARX(1, 256);                          // h complete across GEMM warps

            MBAR_WAIT(u_mb + 16 + 8 * s, pe);      // stage s free?

            if (tid < 64) {                        // stage ea/src/dst
                s_ea4[s * 64 + tid] = eaR;
                s_src[s * 64 + tid] = srcR;
                s_dst[s * 64 + tid] = dstR;
            }

            // ---- phase 2: wt = h @ (0.125*w2), 8 edges x 192 outs per warp
            {
                ull acc[8][3];
#pragma unroll
                for (int a = 0; a < 8; a++)
#pragma unroll
                    for (int b = 0; b < 3; b++) acc[a][b] = 0ull;

#pragma unroll 4
                for (int j = 0; j < 64; j++) {
                    const float4* hp = (const float4*)&s_h[j * 64 + eb];
                    float4 ha = hp[0], hb = hp[1];
                    ull hd[8];
                    hd[0] = fdup(ha.x); hd[1] = fdup(ha.y);
                    hd[2] = fdup(ha.z); hd[3] = fdup(ha.w);
                    hd[4] = fdup(hb.x); hd[5] = fdup(hb.y);
                    hd[6] = fdup(hb.z); hd[7] = fdup(hb.w);
                    const ull* wp = (const ull*)&s_w2[j * 192 + 2 * l];
                    ull b0 = wp[0], b1 = wp[32], b2 = wp[64];
#pragma unroll
                    for (int ee = 0; ee < 8; ee++) {
                        ffma2(acc[ee][0], hd[ee], b0);
                        ffma2(acc[ee][1], hd[ee], b1);
                        ffma2(acc[ee][2], hd[ee], b2);
                    }
                }
                float* wtbuf = (float*)(sb + O_WT + s * 49152);
#pragma unroll
                for (int ee = 0; ee < 8; ee++) {
                    ull* outp = (ull*)&wtbuf[(eb + ee) * 192 + 2 * l];
                    outp[0]  = acc[ee][0];
                    outp[32] = acc[ee][1];
                    outp[64] = acc[ee][2];
                }
            }
            BARX(1, 256);                          // wt/ea staged
            if (tid == 0) MBAR_ARRIVE(u_mb + 8 * s);   // full[s]
        }
    } else {
        // ================= scatter warps (phase 3) =================
        const int sw = wrp - 8;                    // 0 or 1
        float* gw = &s_g[sw * 160];
        float4* gw4 = (float4*)gw;
        int kk = 0;
        for (int tile = blockIdx.x; tile < ntiles; tile += gridDim.x, kk++) {
            const int s = kk & 1;
            const int pf = (kk >> 1) & 1;
            const int e0 = tile * TILE_E;
            MBAR_WAIT(u_mb + 8 * s, pf);           // full[s]

            const float* wtbuf = (const float*)(sb + O_WT + s * 49152);
            const int ebeg = sw * 32;

            float4 pa, pb;
            {
                const float4* fr = (const float4*)&g_f[(size_t)s_src[s * 64 + ebeg] * 160];
                pa = fr[l];
                pb = (l < 8) ? fr[32 + l] : make_float4(0,0,0,0);
            }
            for (int ee = 0; ee < 32; ee++) {
                const int e = ebeg + ee;
                const bool valid = (e0 + e) < E;

                gw4[l] = pa;
                if (l < 8) gw4[32 + l] = pb;
                if (ee < 31) {
                    const float4* fr = (const float4*)&g_f[(size_t)s_src[s * 64 + e + 1] * 160];
                    pa = fr[l];
                    if (l < 8) pb = fr[32 + l];
                }
                __syncwarp();

                float4 ea = s_ea4[s * 64 + e];
                const float ys = ea.x, yv0 = ea.y, yv1 = ea.z, yv2 = ea.w;
                const float* wt = &wtbuf[e * 192];
                float* mb = &g_mid[(size_t)s_dst[s * 64 + e] * 384];

#pragma unroll
                for (int i = 0; i < 3; i++) {
                    const int t0 = i * 128 + 4 * l;
                    float v[4];
                    if (t0 < 64) {                       // m0a
#pragma unroll
                        for (int j = 0; j < 4; j++) v[j] = gw[t0 + j] * ys * wt[t0 + j];
                    } else if (t0 < 96) {                // m0b
                        const int c0 = t0 - 64;
#pragma unroll
                        for (int j = 0; j < 4; j++) {
                            int c = c0 + j;
                            float dot = gw[64 + 3 * c] * yv0 + gw[65 + 3 * c] * yv1
                                      + gw[66 + 3 * c] * yv2;
                            v[j] = dot * 0.5773502691896258f * wt[160 + c];
                        }
                    } else if (t0 < 288) {               // m1a
                        const int s0 = t0 - 96;
#pragma unroll
                        for (int j = 0; j < 4; j++) {
                            int ss2 = s0 + j;
                            int u = ss2 / 3, d = ss2 - 3 * u;
                            float yvd = (d == 0) ? yv0 : ((d == 1) ? yv1 : yv2);
                            v[j] = gw[u] * yvd * wt[64 + u];
                        }
                    } else {                             // m1b
                        const int s0 = t0 - 288;
#pragma unroll
                        for (int j = 0; j < 4; j++) {
                            int ss2 = s0 + j;
                            int u = ss2 / 3;
                            v[j] = gw[64 + ss2] * ys * wt[128 + u];
                        }
                    }
                    if (valid) red4(&mb[t0], v[0], v[1], v[2], v[3]);
                }
                __syncwarp();
            }
            BARX(2, 64);
            if (tid == 256) MBAR_ARRIVE(u_mb + 16 + 8 * s);   // empty[s]
        }
    }
}

// ---------------------------------------------------------------- node post
// 2 nodes per warp; lin2 fctp + angle gate.
#define PST_W0  0
#define PST_W1  24576
#define PST_L3  36864
#define PST_MID 37376
#define PST_SMEM 61952

__global__ __launch_bounds__(256) void k_nodepost(
    const float* __restrict__ attr, const float* __restrict__ l2w0,
    const float* __restrict__ l2w1, const float* __restrict__ l3,
    const int* __restrict__ nn, float* __restrict__ out, int N)
{
    extern __shared__ unsigned char sbq[];
    float* s_w0  = (float*)(sbq + PST_W0);
    float* s_w1  = (float*)(sbq + PST_W1);
    float* s_l3  = (float*)(sbq + PST_L3);
    float* s_mid = (float*)(sbq + PST_MID);   // 16 rows x 384

    for (int i = threadIdx.x; i < 6144; i += 256) s_w0[i] = l2w0[i];
    for (int i = threadIdx.x; i < 3072; i += 256) s_w1[i] = l2w1[i];
    if (threadIdx.x < 96) s_l3[threadIdx.x] = l3[threadIdx.x];

    float ms = rsqrtf((float)nn[0]);
    const float SC = 0.10206207261596575f;
    int wrp = threadIdx.x >> 5, l = threadIdx.x & 31;
    int n0 = blockIdx.x * 16 + wrp * 2;
    int n1 = n0 + 1;
    bool v0 = n0 < N, v1 = n1 < N;
    float* mr0 = &s_mid[(wrp * 2) * 384];
    float* mr1 = &s_mid[(wrp * 2 + 1) * 384];
    if (v0) {
#pragma unroll
        for (int i = 0; i < 12; i++) mr0[l + 32 * i] = g_mid[(size_t)n0 * 384 + l + 32 * i];
    }
    if (v1) {
#pragma unroll
        for (int i = 0; i < 12; i++) mr1[l + 32 * i] = g_mid[(size_t)n1 * 384 + l + 32 * i];
    }
    __syncthreads();
    if (!v0) return;

    float a0 = attr[n0];
    float a1 = v1 ? attr[n1] : 0.f;
    int w_[3], d_[3];
#pragma unroll
    for (int i = 0; i < 3; i++) { int o = l + 32 * i; w_[i] = o / 3; d_[i] = o - 3 * w_[i]; }

    ull c0 = 0ull, c1 = 0ull;
    float ang0 = 0.f, ang1 = 0.f;
#pragma unroll 8
    for (int u = 0; u < 96; u++) {
        ull w = *(const ull*)&s_w0[u * 64 + 2 * l];
        float m0 = mr0[u], m1 = mr1[u];
        ffma2(c0, fdup(m0), w);
        ffma2(c1, fdup(m1), w);
        float lw = s_l3[u];
        ang0 += m0 * lw;
        ang1 += m1 * lw;
    }
    float cv0[3] = {0,0,0}, cv1[3] = {0,0,0};
#pragma unroll 4
    for (int u = 0; u < 96; u++) {
#pragma unroll
        for (int i = 0; i < 3; i++) {
            float w = s_w1[u * 32 + w_[i]];
            cv0[i] += mr0[96 + 3 * u + d_[i]] * w;
            cv1[i] += mr1[96 + 3 * u + d_[i]] * w;
        }
    }
    {
        float sA = SC * ms * a0;
        float angle = 0.1f * ang0 * sA;
        float sa, ca; sincosf(angle, &sa, &ca);
        const float* scrow = &g_sc[(size_t)n0 * 160];
        float* orow = &out[(size_t)n0 * 160];
        float2 cc = funpack(c0);
        float2 sc2 = *(const float2*)&scrow[2 * l];
        *(float2*)&orow[2 * l] = make_float2(ca * sc2.x + sa * (cc.x * sA),
                                             ca * sc2.y + sa * (cc.y * sA));
#pragma unroll
        for (int i = 0; i < 3; i++)
            orow[64 + l + 32 * i] = ca * scrow[64 + l + 32 * i] + sa * (cv0[i] * sA);
    }
    if (v1) {
        float sA = SC * ms * a1;
        float angle = 0.1f * ang1 * sA;
        float sa, ca; sincosf(angle, &sa, &ca);
        const float* scrow = &g_sc[(size_t)n1 * 160];
        float* orow = &out[(size_t)n1 * 160];
        float2 cc = funpack(c1);
        float2 sc2 = *(const float2*)&scrow[2 * l];
        *(float2*)&orow[2 * l] = make_float2(ca * sc2.x + sa * (cc.x * sA),
                                             ca * sc2.y + sa * (cc.y * sA));
#pragma unroll
        for (int i = 0; i < 3; i++)
            orow[64 + l + 32 * i] = ca * scrow[64 + l + 32 * i] + sa * (cv1[i] * sA);
    }
}

// ---------------------------------------------------------------- launch
extern "C" void kernel_launch(void* const* d_in, const int* in_sizes, int n_in,
                              void* d_out, int out_size)
{
    const float* node_input   = (const float*)d_in[0];
    const float* node_attr    = (const float*)d_in[1];
    const float* edge_attr    = (const float*)d_in[2];
    const float* edge_scalars = (const float*)d_in[3];
    const float* sc_w0        = (const float*)d_in[4];
    const float* sc_w1        = (const float*)d_in[5];
    const float* lin1_w0      = (const float*)d_in[6];
    const float* lin1_w1      = (const float*)d_in[7];
    const float* fc_w1        = (const float*)d_in[8];
    const float* fc_w2        = (const float*)d_in[9];
    const float* lin2_w0      = (const float*)d_in[10];
    const float* lin2_w1      = (const float*)d_in[11];
    const float* lin3_w       = (const float*)d_in[12];
    const int*   edge_src     = (const int*)d_in[13];
    const int*   edge_dst     = (const int*)d_in[14];
    const int*   num_neigh    = (const int*)d_in[15];
    float* out = (float*)d_out;

    int N = in_sizes[0] / 160;
    int E = in_sizes[2] / 4;

    cudaFuncSetAttribute(k_nodepre, cudaFuncAttributeMaxDynamicSharedMemorySize, PRE_SMEM);
    k_nodepre<<<(N + 15) / 16, 256, PRE_SMEM>>>(node_input, node_attr, sc_w0, sc_w1,
                                                lin1_w0, lin1_w1, N);

    cudaFuncSetAttribute(k_edge, cudaFuncAttributeMaxDynamicSharedMemorySize, K9_SMEM);
    k_edge<<<148, 320, K9_SMEM>>>(edge_attr, edge_scalars, fc_w1, fc_w2,
                                  edge_src, edge_dst, E);

    cudaFuncSetAttribute(k_nodepost, cudaFuncAttributeMaxDynamicSharedMemorySize, PST_SMEM);
    k_nodepost<<<(N + 15) / 16, 256, PST_SMEM>>>(node_attr, lin2_w0, lin2_w1, lin3_w,
                                                 num_neigh, out, N);
}

// round 11
// speedup vs baseline: 2.0261x; 2.0261x over previous
#include <cuda_runtime.h>
#include <cuda_bf16.h>
#include <cstdint>

// ---------------------------------------------------------------------------
// Convolution_29738353557732 : e3nn-style graph conv
// R10: R8 phased k_edge (fast-div silu) + 2-node-per-warp node kernels.
// ---------------------------------------------------------------------------

#define NMAX 50176
typedef unsigned long long ull;

__device__ float g_f  [NMAX * 160];
__device__ float g_sc [NMAX * 160];
__device__ float g_mid[NMAX * 384];

__device__ __forceinline__ void red4(float* p, float a, float b, float c, float d) {
    asm volatile("red.global.add.v4.f32 [%0], {%1,%2,%3,%4};"
                 :: "l"(p), "f"(a), "f"(b), "f"(c), "f"(d) : "memory");
}
__device__ __forceinline__ ull fdup(float x) {
    ull r; asm("mov.b64 %0, {%1, %1};" : "=l"(r) : "f"(x)); return r;
}
__device__ __forceinline__ void ffma2(ull& acc, ull a, ull b) {
    asm("fma.rn.f32x2 %0, %1, %2, %0;" : "+l"(acc) : "l"(a), "l"(b));
}
__device__ __forceinline__ float2 funpack(ull p) {
    float lo, hi; asm("mov.b64 {%0, %1}, %2;" : "=f"(lo), "=f"(hi) : "l"(p));
    return make_float2(lo, hi);
}

// ---------------------------------------------------------------- node pre
// 2 nodes per warp: weight LDS shared between both nodes. Also zeroes g_mid.
#define PRE_SCW0 0
#define PRE_L1W0 16384
#define PRE_SCW1 32768
#define PRE_L1W1 36864
#define PRE_X    40960
#define PRE_SMEM 51200

__global__ __launch_bounds__(256) void k_nodepre(
    const float* __restrict__ x, const float* __restrict__ attr,
    const float* __restrict__ sc_w0, const float* __restrict__ sc_w1,
    const float* __restrict__ l1w0, const float* __restrict__ l1w1, int N)
{
    extern __shared__ unsigned char sbp[];
    float* s_scw0 = (float*)(sbp + PRE_SCW0);
    float* s_l1w0 = (float*)(sbp + PRE_L1W0);
    float* s_scw1 = (float*)(sbp + PRE_SCW1);
    float* s_l1w1 = (float*)(sbp + PRE_L1W1);
    float* s_x    = (float*)(sbp + PRE_X);     // 16 rows x 160

    {   // zero g_mid (grid-stride)
        float4* m4 = reinterpret_cast<float4*>(g_mid);
        int tot = N * 96;
        int stride = gridDim.x * 256;
        for (int i = blockIdx.x * 256 + threadIdx.x; i < tot; i += stride)
            m4[i] = make_float4(0.f, 0.f, 0.f, 0.f);
    }

    for (int i = threadIdx.x; i < 4096; i += 256) { s_scw0[i] = sc_w0[i]; s_l1w0[i] = l1w0[i]; }
    for (int i = threadIdx.x; i < 1024; i += 256) { s_scw1[i] = sc_w1[i]; s_l1w1[i] = l1w1[i]; }

    int wrp = threadIdx.x >> 5, l = threadIdx.x & 31;
    int n0 = blockIdx.x * 16 + wrp * 2;
    int n1 = n0 + 1;
    bool v0 = n0 < N, v1 = n1 < N;
    float* xr0 = &s_x[(wrp * 2) * 160];
    float* xr1 = &s_x[(wrp * 2 + 1) * 160];
    if (v0) {
#pragma unroll
        for (int i = 0; i < 5; i++) xr0[l + 32 * i] = x[(size_t)n0 * 160 + l + 32 * i];
    }
    if (v1) {
#pragma unroll
        for (int i = 0; i < 5; i++) xr1[l + 32 * i] = x[(size_t)n1 * 160 + l + 32 * i];
    }
    __syncthreads();
    if (!v0) return;

    float a0 = attr[n0];
    float a1 = v1 ? attr[n1] : 0.f;
    int w_[3], d_[3];
#pragma unroll
    for (int i = 0; i < 3; i++) { int o = l + 32 * i; w_[i] = o / 3; d_[i] = o - 3 * w_[i]; }

    ull af0 = 0ull, as0 = 0ull, af1 = 0ull, as1 = 0ull;
#pragma unroll 8
    for (int u = 0; u < 64; u++) {
        ull wl = *(const ull*)&s_l1w0[u * 64 + 2 * l];
        ull ws = *(const ull*)&s_scw0[u * 64 + 2 * l];
        ull x0 = fdup(xr0[u]);
        ull x1 = fdup(xr1[u]);
        ffma2(af0, x0, wl); ffma2(as0, x0, ws);
        ffma2(af1, x1, wl); ffma2(as1, x1, ws);
    }
    float fv0[3] = {0,0,0}, sv0[3] = {0,0,0}, fv1[3] = {0,0,0}, sv1[3] = {0,0,0};
#pragma unroll 4
    for (int u = 0; u < 32; u++) {
#pragma unroll
        for (int i = 0; i < 3; i++) {
            float wl = s_l1w1[u * 32 + w_[i]];
            float ws = s_scw1[u * 32 + w_[i]];
            float xv0 = xr0[64 + 3 * u + d_[i]];
            float xv1 = xr1[64 + 3 * u + d_[i]];
            fv0[i] += xv0 * wl;  sv0[i] += xv0 * ws;
            fv1[i] += xv1 * wl;  sv1[i] += xv1 * ws;
        }
    }
    {
        float* fo = &g_f[(size_t)n0 * 160];
        float* so = &g_sc[(size_t)n0 * 160];
        float S1 = 0.125f * a0, S2 = 0.17677669529663687f * a0;
        float2 ff = funpack(af0), ss = funpack(as0);
        *(float2*)&fo[2 * l] = make_float2(ff.x * S1, ff.y * S1);
        *(float2*)&so[2 * l] = make_float2(ss.x * S1, ss.y * S1);
#pragma unroll
        for (int i = 0; i < 3; i++) {
            fo[64 + l + 32 * i] = fv0[i] * S2;
            so[64 + l + 32 * i] = sv0[i] * S2;
        }
    }
    if (v1) {
        float* fo = &g_f[(size_t)n1 * 160];
        float* so = &g_sc[(size_t)n1 * 160];
        float S1 = 0.125f * a1, S2 = 0.17677669529663687f * a1;
        float2 ff = funpack(af1), ss = funpack(as1);
        *(float2*)&fo[2 * l] = make_float2(ff.x * S1, ff.y * S1);
        *(float2*)&so[2 * l] = make_float2(ss.x * S1, ss.y * S1);
#pragma unroll
        for (int i = 0; i < 3; i++) {
            fo[64 + l + 32 * i] = fv1[i] * S2;
            so[64 + l + 32 * i] = sv1[i] * S2;
        }
    }
}

// ---------------------------------------------------------------- edge kernel
// TILE_E=48, 256 threads, 2 CTAs/SM (R8 structure, fast-div silu).
#define TILE_E 48

#define O_H    0                    // 64*48*4      = 12288
#define O_W2   12288                // 12288 f      = 49152
#define O_WT   61440                // 48*192*4     = 36864
#define O_W1   98304                // 2048
#define O_ES   100352               // 48*9*4       = 1728
#define O_EA   102080               // 48*4*4       = 768
#define O_SRC  102848               // 192
#define O_DST  103040               // 192
#define O_G    103232               // 8*160*4      = 5120
#define K5_SMEM 108352

__global__ __launch_bounds__(256, 2) void k_edge(
    const float* __restrict__ edge_attr, const float* __restrict__ edge_scalars,
    const float* __restrict__ fc_w1, const float* __restrict__ fc_w2,
    const int* __restrict__ edge_src, const int* __restrict__ edge_dst, int E)
{
    extern __shared__ unsigned char sb[];
    float* s_h  = (float*)(sb + O_H);
    float* s_w2 = (float*)(sb + O_W2);
    float* s_wt = (float*)(sb + O_WT);
    float* s_w1 = (float*)(sb + O_W1);
    float* s_es = (float*)(sb + O_ES);
    float* s_ea = (float*)(sb + O_EA);
    int*   s_src = (int*)(sb + O_SRC);
    int*   s_dst = (int*)(sb + O_DST);
    float* s_g  = (float*)(sb + O_G);

    const int tid = threadIdx.x;
    const int wrp = tid >> 5, l = tid & 31;

    for (int i = tid; i < 512; i += 256) s_w1[i] = fc_w1[i];
    for (int i = tid; i < 12288; i += 256) s_w2[i] = fc_w2[i] * 0.125f;
    __syncthreads();

    const int ntiles = (E + TILE_E - 1) / TILE_E;
    const int eb = wrp * 6;   // phase-2/3 edge base for this warp

    for (int tile = blockIdx.x; tile < ntiles; tile += gridDim.x) {
        const int e0 = tile * TILE_E;

        // ---- stage per-edge inputs
        for (int i = tid; i < 48 * 8; i += 256) {
            int e = i >> 3, c = i & 7, ge = e0 + e;
            s_es[e * 9 + c] = (ge < E) ? edge_scalars[(size_t)ge * 8 + c] : 0.f;
        }
        if (tid < 192) {
            int e = tid >> 2, c = tid & 3, ge = e0 + e;
            s_ea[e * 4 + c] = (ge < E) ? edge_attr[(size_t)ge * 4 + c] : 0.f;
        }
        if (tid < 48) {
            int ge = e0 + tid;
            s_src[tid] = (ge < E) ? edge_src[ge] : 0;
            s_dst[tid] = (ge < E) ? edge_dst[ge] : 0;
        }
        __syncthreads();

        // ---- phase 1: h = silu(es @ fc_w1 / sqrt(8)) -> s_h[j*48+e]
        for (int i = tid; i < 48 * 64; i += 256) {
            int e = i % 48, j = i / 48;
            const float* es = &s_es[e * 9];
            float acc = 0.f;
#pragma unroll
            for (int c = 0; c < 8; c++) acc += es[c] * s_w1[c * 64 + j];
            acc *= 0.3535533905932738f;
            s_h[j * 48 + e] = __fdividef(acc, 1.f + __expf(-acc));
        }
        __syncthreads();

        // ---- phase 2: wt = h @ (0.125*w2); warp = 6 edges x 192 outs
        {
            ull acc[6][3];
#pragma unroll
            for (int a = 0; a < 6; a++)
#pragma unroll
                for (int b = 0; b < 3; b++) acc[a][b] = 0ull;

#pragma unroll 4
            for (int j = 0; j < 64; j++) {
                const float2* hp = (const float2*)&s_h[j * 48 + eb];
                float2 h01 = hp[0], h23 = hp[1], h45 = hp[2];
                ull hd[6];
                hd[0] = fdup(h01.x); hd[1] = fdup(h01.y);
                hd[2] = fdup(h23.x); hd[3] = fdup(h23.y);
                hd[4] = fdup(h45.x); hd[5] = fdup(h45.y);
                const ull* wp = (const ull*)&s_w2[j * 192 + 2 * l];
                ull w0 = wp[0], w1v = wp[32], w2v = wp[64];
#pragma unroll
                for (int e = 0; e < 6; e++) {
                    ffma2(acc[e][0], hd[e], w0);
                    ffma2(acc[e][1], hd[e], w1v);
                    ffma2(acc[e][2], hd[e], w2v);
                }
            }
#pragma unroll
            for (int e = 0; e < 6; e++) {
                ull* outp = (ull*)&s_wt[(eb + e) * 192 + 2 * l];
                outp[0]  = acc[e][0];
                outp[32] = acc[e][1];
                outp[64] = acc[e][2];
            }
        }
        __syncthreads();

        // ---- phase 3: prefetched gather + features + red.v4 scatter
        {
            float* gw = &s_g[wrp * 160];
            float4* gw4 = (float4*)gw;

            float4 pa, pb;
            {
                const float4* fr = (const float4*)&g_f[(size_t)s_src[eb] * 160];
                pa = fr[l];
                pb = (l < 8) ? fr[32 + l] : make_float4(0.f, 0.f, 0.f, 0.f);
            }

#pragma unroll
            for (int ee = 0; ee < 6; ee++) {
                const int e = eb + ee;
                const bool valid = (e0 + e) < E;

                gw4[l] = pa;
                if (l < 8) gw4[32 + l] = pb;
                if (ee < 5) {
                    const float4* fr = (const float4*)&g_f[(size_t)s_src[e + 1] * 160];
                    pa = fr[l];
                    if (l < 8) pb = fr[32 + l];
                }
                __syncwarp();

                const float ys  = s_ea[e * 4 + 0];
                const float yv0 = s_ea[e * 4 + 1];
                const float yv1 = s_ea[e * 4 + 2];
                const float yv2 = s_ea[e * 4 + 3];
                const float* wt = &s_wt[e * 192];
                float* mb = &g_mid[(size_t)s_dst[e] * 384];

#pragma unroll
                for (int i = 0; i < 3; i++) {
                    const int t0 = i * 128 + 4 * l;
                    float v[4];
                    if (t0 < 64) {                       // m0a
#pragma unroll
                        for (int j = 0; j < 4; j++) v[j] = gw[t0 + j] * ys * wt[t0 + j];
                    } else if (t0 < 96) {                // m0b
                        const int c0 = t0 - 64;
#pragma unroll
                        for (int j = 0; j < 4; j++) {
                            int c = c0 + j;
                            float dot = gw[64 + 3 * c] * yv0 + gw[65 + 3 * c] * yv1
                                      + gw[66 + 3 * c] * yv2;
                            v[j] = dot * 0.5773502691896258f * wt[160 + c];
                        }
                    } else if (t0 < 288) {               // m1a
                        const int s0 = t0 - 96;
#pragma unroll
                        for (int j = 0; j < 4; j++) {
                            int s = s0 + j;
                            int u = s / 3, d = s - 3 * u;
                            float yvd = (d == 0) ? yv0 : ((d == 1) ? yv1 : yv2);
                            v[j] = gw[u] * yvd * wt[64 + u];
                        }
                    } else {                             // m1b
                        const int s0 = t0 - 288;
#pragma unroll
                        for (int j = 0; j < 4; j++) {
                            int s = s0 + j;
                            int u = s / 3;
                            v[j] = gw[64 + s] * ys * wt[128 + u];
                        }
                    }
                    if (valid) red4(&mb[t0], v[0], v[1], v[2], v[3]);
                }
                __syncwarp();
            }
        }
        __syncthreads();
    }
}

// ---------------------------------------------------------------- node post
// 2 nodes per warp; lin2 fctp + angle gate.
#define PST_W0  0
#define PST_W1  24576
#define PST_L3  36864
#define PST_MID 37376
#define PST_SMEM 61952

__global__ __launch_bounds__(256) void k_nodepost(
    const float* __restrict__ attr, const float* __restrict__ l2w0,
    const float* __restrict__ l2w1, const float* __restrict__ l3,
    const int* __restrict__ nn, float* __restrict__ out, int N)
{
    extern __shared__ unsigned char sbq[];
    float* s_w0  = (float*)(sbq + PST_W0);
    float* s_w1  = (float*)(sbq + PST_W1);
    float* s_l3  = (float*)(sbq + PST_L3);
    float* s_mid = (float*)(sbq + PST_MID);   // 16 rows x 384

    for (int i = threadIdx.x; i < 6144; i += 256) s_w0[i] = l2w0[i];
    for (int i = threadIdx.x; i < 3072; i += 256) s_w1[i] = l2w1[i];
    if (threadIdx.x < 96) s_l3[threadIdx.x] = l3[threadIdx.x];

    float ms = rsqrtf((float)nn[0]);
    const float SC = 0.10206207261596575f;
    int wrp = threadIdx.x >> 5, l = threadIdx.x & 31;
    int n0 = blockIdx.x * 16 + wrp * 2;
    int n1 = n0 + 1;
    bool v0 = n0 < N, v1 = n1 < N;
    float* mr0 = &s_mid[(wrp * 2) * 384];
    float* mr1 = &s_mid[(wrp * 2 + 1) * 384];
    if (v0) {
#pragma unroll
        for (int i = 0; i < 12; i++) mr0[l + 32 * i] = g_mid[(size_t)n0 * 384 + l + 32 * i];
    }
    if (v1) {
#pragma unroll
        for (int i = 0; i < 12; i++) mr1[l + 32 * i] = g_mid[(size_t)n1 * 384 + l + 32 * i];
    }
    __syncthreads();
    if (!v0) return;

    float a0 = attr[n0];
    float a1 = v1 ? attr[n1] : 0.f;
    int w_[3], d_[3];
#pragma unroll
    for (int i = 0; i < 3; i++) { int o = l + 32 * i; w_[i] = o / 3; d_[i] = o - 3 * w_[i]; }

    ull c0 = 0ull, c1 = 0ull;
    float ang0 = 0.f, ang1 = 0.f;
#pragma unroll 8
    for (int u = 0; u < 96; u++) {
        ull w = *(const ull*)&s_w0[u * 64 + 2 * l];
        float m0 = mr0[u], m1 = mr1[u];
        ffma2(c0, fdup(m0), w);
        ffma2(c1, fdup(m1), w);
        float lw = s_l3[u];
        ang0 += m0 * lw;
        ang1 += m1 * lw;
    }
    float cv0[3] = {0,0,0}, cv1[3] = {0,0,0};
#pragma unroll 4
    for (int u = 0; u < 96; u++) {
#pragma unroll
        for (int i = 0; i < 3; i++) {
            float w = s_w1[u * 32 + w_[i]];
            cv0[i] += mr0[96 + 3 * u + d_[i]] * w;
            cv1[i] += mr1[96 + 3 * u + d_[i]] * w;
        }
    }
    {
        float sA = SC * ms * a0;
        float angle = 0.1f * ang0 * sA;
        float sa, ca; sincosf(angle, &sa, &ca);
        const float* scrow = &g_sc[(size_t)n0 * 160];
        float* orow = &out[(size_t)n0 * 160];
        float2 cc = funpack(c0);
        float2 sc2 = *(const float2*)&scrow[2 * l];
        *(float2*)&orow[2 * l] = make_float2(ca * sc2.x + sa * (cc.x * sA),
                                             ca * sc2.y + sa * (cc.y * sA));
#pragma unroll
        for (int i = 0; i < 3; i++)
            orow[64 + l + 32 * i] = ca * scrow[64 + l + 32 * i] + sa * (cv0[i] * sA);
    }
    if (v1) {
        float sA = SC * ms * a1;
        float angle = 0.1f * ang1 * sA;
        float sa, ca; sincosf(angle, &sa, &ca);
        const float* scrow = &g_sc[(size_t)n1 * 160];
        float* orow = &out[(size_t)n1 * 160];
        float2 cc = funpack(c1);
        float2 sc2 = *(const float2*)&scrow[2 * l];
        *(float2*)&orow[2 * l] = make_float2(ca * sc2.x + sa * (cc.x * sA),
                                             ca * sc2.y + sa * (cc.y * sA));
#pragma unroll
        for (int i = 0; i < 3; i++)
            orow[64 + l + 32 * i] = ca * scrow[64 + l + 32 * i] + sa * (cv1[i] * sA);
    }
}

// ---------------------------------------------------------------- launch
extern "C" void kernel_launch(void* const* d_in, const int* in_sizes, int n_in,
                              void* d_out, int out_size)
{
    const float* node_input   = (const float*)d_in[0];
    const float* node_attr    = (const float*)d_in[1];
    const float* edge_attr    = (const float*)d_in[2];
    const float* edge_scalars = (const float*)d_in[3];
    const float* sc_w0        = (const float*)d_in[4];
    const float* sc_w1        = (const float*)d_in[5];
    const float* lin1_w0      = (const float*)d_in[6];
    const float* lin1_w1      = (const float*)d_in[7];
    const float* fc_w1        = (const float*)d_in[8];
    const float* fc_w2        = (const float*)d_in[9];
    const float* lin2_w0      = (const float*)d_in[10];
    const float* lin2_w1      = (const float*)d_in[11];
    const float* lin3_w       = (const float*)d_in[12];
    const int*   edge_src     = (const int*)d_in[13];
    const int*   edge_dst     = (const int*)d_in[14];
    const int*   num_neigh    = (const int*)d_in[15];
    float* out = (float*)d_out;

    int N = in_sizes[0] / 160;
    int E = in_sizes[2] / 4;

    cudaFuncSetAttribute(k_nodepre, cudaFuncAttributeMaxDynamicSharedMemorySize, PRE_SMEM);
    k_nodepre<<<(N + 15) / 16, 256, PRE_SMEM>>>(node_input, node_attr, sc_w0, sc_w1,
                                                lin1_w0, lin1_w1, N);

    cudaFuncSetAttribute(k_edge, cudaFuncAttributeMaxDynamicSharedMemorySize, K5_SMEM);
    k_edge<<<296, 256, K5_SMEM>>>(edge_attr, edge_scalars, fc_w1, fc_w2,
                                  edge_src, edge_dst, E);

    cudaFuncSetAttribute(k_nodepost, cudaFuncAttributeMaxDynamicSharedMemorySize, PST_SMEM);
    k_nodepost<<<(N + 15) / 16, 256, PST_SMEM>>>(node_attr, lin2_w0, lin2_w1, lin3_w,
                                                 num_neigh, out, N);
}